// round 1
// baseline (speedup 1.0000x reference)
#include <cuda_runtime.h>

// Problem constants (fixed by the reference setup)
#define B_  32
#define T_  256
#define F_  64
#define C_  16
#define CO_ 16
#define P_  64
#define S_  32
#define K_  4
#define DIL 2
#define LPAD 6              // DIL*(K_-1)
#define FC  1024            // F_*C_
#define KIN 1056            // FC + S_
#define OUTC 96             // C_ + CO_ + P_
#define ROWS (B_*T_)        // 8192

// ============================================================================
// Kernel A: pointwise GEMM  out_rows[8192, 64] = point_in[8192,1056] @ W_p + b_p
// then ReLU and broadcast-write into out[..., 32:96] for all 64 features.
// Tile: BM=32 rows, BN=64 cols, BK=32. 256 threads, 2x4 micro-tile per thread.
// ============================================================================
__global__ __launch_bounds__(256, 4)
void tpc_point_kernel(const float* __restrict__ x,
                      const float* __restrict__ stat,
                      const float* __restrict__ W_p,
                      const float* __restrict__ b_p,
                      float* __restrict__ out)
{
    __shared__ __align__(16) float As[32][33];   // padded to avoid bank conflicts
    __shared__ __align__(16) float Bs[32][64];
    __shared__ __align__(16) float Ps[32][64];   // relu(point_out) tile

    const int tid  = threadIdx.x;
    const int row0 = blockIdx.x * 32;          // 256 blocks
    const int m0   = (tid >> 4) * 2;           // 0..30
    const int n0   = (tid & 15) * 4;           // 0..60

    float acc[2][4] = {};

    for (int kb = 0; kb < 33; ++kb) {          // 33 * 32 = 1056 = KIN
        const int kg0 = kb * 32;

        // --- load A tile: 32 rows x 32 k (coalesced 128B per row) ---
        #pragma unroll
        for (int l = 0; l < 4; ++l) {
            int idx = tid + l * 256;           // 0..1023
            int i   = idx >> 5;
            int kk  = idx & 31;
            int kg  = kg0 + kk;
            int row = row0 + i;
            float v;
            if (kg < FC) v = x[row * FC + kg];
            else         v = stat[(row >> 8) * S_ + (kg - FC)];
            As[i][kk] = v;
        }
        // --- load B tile: 32 k x 64 n (coalesced) ---
        #pragma unroll
        for (int l = 0; l < 8; ++l) {
            int idx = tid + l * 256;           // 0..2047
            int kk  = idx >> 6;
            int nn  = idx & 63;
            Bs[kk][nn] = W_p[(kg0 + kk) * P_ + nn];
        }
        __syncthreads();

        #pragma unroll
        for (int kk = 0; kk < 32; ++kk) {
            float a0 = As[m0][kk];
            float a1 = As[m0 + 1][kk];
            float4 b4 = *reinterpret_cast<const float4*>(&Bs[kk][n0]);
            acc[0][0] += a0 * b4.x; acc[0][1] += a0 * b4.y;
            acc[0][2] += a0 * b4.z; acc[0][3] += a0 * b4.w;
            acc[1][0] += a1 * b4.x; acc[1][1] += a1 * b4.y;
            acc[1][2] += a1 * b4.z; acc[1][3] += a1 * b4.w;
        }
        __syncthreads();
    }

    // bias + relu into shared result tile
    {
        float4 bb = *reinterpret_cast<const float4*>(&b_p[n0]);
        #pragma unroll
        for (int i = 0; i < 2; ++i) {
            Ps[m0 + i][n0 + 0] = fmaxf(acc[i][0] + bb.x, 0.f);
            Ps[m0 + i][n0 + 1] = fmaxf(acc[i][1] + bb.y, 0.f);
            Ps[m0 + i][n0 + 2] = fmaxf(acc[i][2] + bb.z, 0.f);
            Ps[m0 + i][n0 + 3] = fmaxf(acc[i][3] + bb.w, 0.f);
        }
    }
    __syncthreads();

    // broadcast write: for each of 32 rows, replicate 64 floats across 64 features.
    // 32 rows * 64 f * 16 float4 = 32768 float4 / 256 threads = 128 iterations.
    #pragma unroll 4
    for (int it = 0; it < 128; ++it) {
        int flat = it * 256 + tid;
        int q    = flat & 15;          // float4 index within the 64-wide P chunk
        int f    = (flat >> 4) & 63;
        int r    = flat >> 10;         // tile row
        int row  = row0 + r;
        float4 v = *reinterpret_cast<const float4*>(&Ps[r][q * 4]);
        *reinterpret_cast<float4*>(&out[(size_t)(row * F_ + f) * OUTC + 32 + q * 4]) = v;
    }
}

// ============================================================================
// Kernel B: causal dilated conv per (b, f) + x passthrough.
// Block = one (b,f). Filter (4KB) + full T slab of x (16.4KB padded) in smem.
// Thread micro-tile: 4 t x 4 co. Writes out[..., 0:16] (relu x) and [16:32].
// ============================================================================
__global__ __launch_bounds__(256, 4)
void tpc_conv_kernel(const float* __restrict__ x,
                     const float* __restrict__ conv_w,
                     const float* __restrict__ conv_b,
                     float* __restrict__ out)
{
    // xs rows padded to 17 floats to avoid 8-way bank conflicts on strided t reads
    __shared__ __align__(16) float xs[(T_ + LPAD) * 17];  // (262)*17 floats
    __shared__ __align__(16) float ws[64 * 16];           // [c*4+k][co]
    __shared__ float bs[CO_];

    const int tid = threadIdx.x;
    const int b   = blockIdx.x >> 6;
    const int f   = blockIdx.x & 63;

    // zero the left-pad rows (times -6..-1 -> xs rows 0..5)
    if (tid < LPAD * 17) xs[tid] = 0.f;

    // load filter, transposed to [ck][co] so co is contiguous in smem
    #pragma unroll
    for (int l = 0; l < 4; ++l) {
        int idx = tid + l * 256;            // = co*64 + ck in global layout
        int co  = idx >> 6;
        int ck  = idx & 63;
        ws[ck * 16 + co] = conv_w[f * 1024 + idx];
    }
    if (tid < CO_) bs[tid] = conv_b[f * CO_ + tid];

    // load x slab: x[b, t, f, 0:16] for t = 0..255
    const float* xb = x + ((size_t)(b * T_) * F_ + f) * C_;
    #pragma unroll
    for (int l = 0; l < 16; ++l) {
        int idx = tid + l * 256;            // t*16 + c
        int t   = idx >> 4;
        int c   = idx & 15;
        xs[(t + LPAD) * 17 + c] = xb[(size_t)t * FC + c];
    }
    __syncthreads();

    // compute: thread handles t0..t0+3, co0..co0+3
    const int tg  = tid >> 2;               // 0..63
    const int cq  = tid & 3;                // 0..3
    const int t0  = tg * 4;
    const int co0 = cq * 4;

    float acc[4][4] = {};
    #pragma unroll
    for (int k = 0; k < K_; ++k) {
        #pragma unroll
        for (int c = 0; c < C_; ++c) {
            float4 w4 = *reinterpret_cast<const float4*>(&ws[(c * 4 + k) * 16 + co0]);
            #pragma unroll
            for (int i = 0; i < 4; ++i) {
                // time (t0+i) needs x at (t0+i) - LPAD + 2k  -> xs row (t0+i) + 2k
                float a = xs[(t0 + i + 2 * k) * 17 + c];
                acc[i][0] += a * w4.x;
                acc[i][1] += a * w4.y;
                acc[i][2] += a * w4.z;
                acc[i][3] += a * w4.w;
            }
        }
    }

    float* ob = out + ((size_t)(b * T_) * F_ + f) * OUTC;   // + t*F_*OUTC + ch

    // temp_out slice [16:32): bias + relu, float4 stores
    {
        float4 bb = *reinterpret_cast<const float4*>(&bs[co0]);
        #pragma unroll
        for (int i = 0; i < 4; ++i) {
            float4 v;
            v.x = fmaxf(acc[i][0] + bb.x, 0.f);
            v.y = fmaxf(acc[i][1] + bb.y, 0.f);
            v.z = fmaxf(acc[i][2] + bb.z, 0.f);
            v.w = fmaxf(acc[i][3] + bb.w, 0.f);
            *reinterpret_cast<float4*>(&ob[(size_t)(t0 + i) * (F_ * OUTC) + 16 + co0]) = v;
        }
    }

    // x passthrough slice [0:16): relu(x)
    #pragma unroll
    for (int l = 0; l < 16; ++l) {
        int idx = tid + l * 256;
        int t   = idx >> 4;
        int c   = idx & 15;
        ob[(size_t)t * (F_ * OUTC) + c] = fmaxf(xs[(t + LPAD) * 17 + c], 0.f);
    }
}

// ============================================================================
// Launch
// ============================================================================
extern "C" void kernel_launch(void* const* d_in, const int* in_sizes, int n_in,
                              void* d_out, int out_size)
{
    const float* x      = (const float*)d_in[0];   // [32,256,64,16]
    const float* statv  = (const float*)d_in[1];   // [32,32]
    const float* conv_w = (const float*)d_in[2];   // [64,16,16,4]
    const float* conv_b = (const float*)d_in[3];   // [64,16]
    const float* W_p    = (const float*)d_in[4];   // [1056,64]
    const float* b_p    = (const float*)d_in[5];   // [64]
    // d_in[6] = dilation (always 2, hardcoded)
    float* out = (float*)d_out;                    // [32,256,64,96]

    tpc_point_kernel<<<ROWS / 32, 256>>>(x, statv, W_p, b_p, out);
    tpc_conv_kernel<<<B_ * F_, 256>>>(x, conv_w, conv_b, out);
}

// round 3
// speedup vs baseline: 1.0787x; 1.0787x over previous
#include <cuda_runtime.h>

// Problem constants (fixed by the reference setup)
#define B_   32
#define T_   256
#define F_   64
#define C_   16
#define CO_  16
#define P_   64
#define S_   32
#define K_   4
#define LPAD 6               // dilation*(K-1)
#define FC   1024            // F_*C_
#define KIN  1056            // FC + S_
#define OUTC 96              // C_ + CO_ + P_
#define ROWS (B_*T_)         // 8192

// Point-GEMM tiling
#define PBLKS 64
#define BM    128
#define BK    16
#define AS_S  136            // padded stride for k-major A tile

// compact relu(point_out) scratch: 8192 x 64 fp32 = 2 MB
__device__ float g_point[ROWS * P_];

// ---------------- packed f32x2 helpers ----------------
__device__ __forceinline__ double pack2(float lo, float hi) {
    double d; asm("mov.b64 %0, {%1, %2};" : "=d"(d) : "f"(lo), "f"(hi)); return d;
}
__device__ __forceinline__ float2 unpack2(double d) {
    float2 v; asm("mov.b64 {%0, %1}, %2;" : "=f"(v.x), "=f"(v.y) : "d"(d)); return v;
}
__device__ __forceinline__ void fma2(double& acc, double a, double b) {
    asm("fma.rn.f32x2 %0, %1, %2, %3;" : "=d"(acc) : "d"(a), "d"(b), "d"(acc));
}

struct SmemP {                                 // point role: ~12.8 KB
    alignas(16) float AsT[BK][AS_S];
    alignas(16) float Bs[BK][P_];
};
struct SmemC {                                 // conv role: ~22 KB
    alignas(16) float xs[(T_ + LPAD) * 17 + 2];  // padded to 16B multiple
    alignas(16) float ws[64 * 16];               // [c*4+k][co]
    alignas(16) float bs[CO_];
};
union SmemU { SmemP p; SmemC c; };

// ============================================================================
// Fused kernel. blocks [0,64): point GEMM -> g_point (relu'd, compact).
//               blocks [64, 64+2048): conv per (b,f) -> out[...,0:32].
// ============================================================================
__global__ __launch_bounds__(256, 2)
void tpc_fused(const float* __restrict__ x,
               const float* __restrict__ stat,
               const float* __restrict__ conv_w,
               const float* __restrict__ conv_b,
               const float* __restrict__ W_p,
               const float* __restrict__ b_p,
               float* __restrict__ out)
{
    __shared__ __align__(16) SmemU sm;
    const int tid = threadIdx.x;

    if (blockIdx.x < PBLKS) {
        // ------------------- POINT GEMM ROLE -------------------
        const int row0 = blockIdx.x * BM;
        const int n0   = (tid & 15) * 4;       // 16 n-groups of 4
        const int m0   = (tid >> 4) * 8;       // 16 m-groups of 8

        double acc[4][4];                       // [m-pair][n], each = 2 m-rows
        #pragma unroll
        for (int i = 0; i < 4; ++i)
            #pragma unroll
            for (int j = 0; j < 4; ++j) acc[i][j] = 0.0;

        for (int kb = 0; kb < KIN / BK; ++kb) {  // 66 iterations
            const int kg0 = kb * BK;
            // load A tile transposed to k-major [kk][m]
            #pragma unroll
            for (int l = 0; l < 2; ++l) {
                int flat = tid + l * 256;       // 0..511 float4s
                int r    = flat >> 2;           // 0..127
                int kq   = flat & 3;
                int kgf  = kg0 + kq * 4;
                float4 v;
                if (kgf < FC)
                    v = *reinterpret_cast<const float4*>(&x[(size_t)(row0 + r) * FC + kgf]);
                else
                    v = *reinterpret_cast<const float4*>(&stat[((row0 + r) >> 8) * S_ + (kgf - FC)]);
                sm.p.AsT[kq * 4 + 0][r] = v.x;
                sm.p.AsT[kq * 4 + 1][r] = v.y;
                sm.p.AsT[kq * 4 + 2][r] = v.z;
                sm.p.AsT[kq * 4 + 3][r] = v.w;
            }
            // load B tile [kk][n] (vectorized, exact fit: 256 float4)
            {
                int kk = tid >> 4;
                int nq = tid & 15;
                *reinterpret_cast<float4*>(&sm.p.Bs[kk][nq * 4]) =
                    *reinterpret_cast<const float4*>(&W_p[(size_t)(kg0 + kk) * P_ + nq * 4]);
            }
            __syncthreads();

            #pragma unroll
            for (int kk = 0; kk < BK; ++kk) {
                float4 a01 = *reinterpret_cast<const float4*>(&sm.p.AsT[kk][m0]);
                float4 a23 = *reinterpret_cast<const float4*>(&sm.p.AsT[kk][m0 + 4]);
                float4 b4  = *reinterpret_cast<const float4*>(&sm.p.Bs[kk][n0]);
                double ad0 = pack2(a01.x, a01.y), ad1 = pack2(a01.z, a01.w);
                double ad2 = pack2(a23.x, a23.y), ad3 = pack2(a23.z, a23.w);
                double bd0 = pack2(b4.x, b4.x),  bd1 = pack2(b4.y, b4.y);
                double bd2 = pack2(b4.z, b4.z),  bd3 = pack2(b4.w, b4.w);
                fma2(acc[0][0], ad0, bd0); fma2(acc[0][1], ad0, bd1);
                fma2(acc[0][2], ad0, bd2); fma2(acc[0][3], ad0, bd3);
                fma2(acc[1][0], ad1, bd0); fma2(acc[1][1], ad1, bd1);
                fma2(acc[1][2], ad1, bd2); fma2(acc[1][3], ad1, bd3);
                fma2(acc[2][0], ad2, bd0); fma2(acc[2][1], ad2, bd1);
                fma2(acc[2][2], ad2, bd2); fma2(acc[2][3], ad2, bd3);
                fma2(acc[3][0], ad3, bd0); fma2(acc[3][1], ad3, bd1);
                fma2(acc[3][2], ad3, bd2); fma2(acc[3][3], ad3, bd3);
            }
            __syncthreads();
        }

        // epilogue: bias + relu -> compact scratch
        float4 bb = *reinterpret_cast<const float4*>(&b_p[n0]);
        #pragma unroll
        for (int mq = 0; mq < 4; ++mq) {
            float2 p0 = unpack2(acc[mq][0]);
            float2 p1 = unpack2(acc[mq][1]);
            float2 p2 = unpack2(acc[mq][2]);
            float2 p3 = unpack2(acc[mq][3]);
            float4 lo, hi;
            lo.x = fmaxf(p0.x + bb.x, 0.f); lo.y = fmaxf(p1.x + bb.y, 0.f);
            lo.z = fmaxf(p2.x + bb.z, 0.f); lo.w = fmaxf(p3.x + bb.w, 0.f);
            hi.x = fmaxf(p0.y + bb.x, 0.f); hi.y = fmaxf(p1.y + bb.y, 0.f);
            hi.z = fmaxf(p2.y + bb.z, 0.f); hi.w = fmaxf(p3.y + bb.w, 0.f);
            int row = row0 + m0 + 2 * mq;
            *reinterpret_cast<float4*>(&g_point[(size_t)row * P_ + n0])       = lo;
            *reinterpret_cast<float4*>(&g_point[(size_t)(row + 1) * P_ + n0]) = hi;
        }
    } else {
        // ------------------- CONV ROLE -------------------
        const int cb = blockIdx.x - PBLKS;
        const int b  = cb >> 6;
        const int f  = cb & 63;

        // zero left-pad rows (times -6..-1 -> xs rows 0..5)
        if (tid < LPAD * 17) sm.c.xs[tid] = 0.f;

        // filter transposed to [ck][co]
        #pragma unroll
        for (int l = 0; l < 4; ++l) {
            int idx = tid + l * 256;         // = co*64 + ck in global layout
            int co  = idx >> 6;
            int ck  = idx & 63;
            sm.c.ws[ck * 16 + co] = conv_w[f * 1024 + idx];
        }
        if (tid < CO_) sm.c.bs[tid] = conv_b[f * CO_ + tid];

        // x slab: x[b, t, f, 0:16]
        const float* xb = x + ((size_t)(b * T_) * F_ + f) * C_;
        #pragma unroll
        for (int l = 0; l < 16; ++l) {
            int idx = tid + l * 256;         // t*16 + c
            int t   = idx >> 4;
            int c   = idx & 15;
            sm.c.xs[(t + LPAD) * 17 + c] = xb[(size_t)t * FC + c];
        }
        __syncthreads();

        const int tg  = tid >> 2;            // 0..63
        const int cq  = tid & 3;
        const int t0  = tg * 4;
        const int co0 = cq * 4;

        double acc2[4][2];                    // [t][co-pair] (2 co each)
        #pragma unroll
        for (int i = 0; i < 4; ++i) { acc2[i][0] = 0.0; acc2[i][1] = 0.0; }

        #pragma unroll 4
        for (int c = 0; c < C_; ++c) {
            // register-cache the 10 activation rows this thread needs
            double ad[10];
            #pragma unroll
            for (int r = 0; r < 10; ++r) {
                float a = sm.c.xs[(t0 + r) * 17 + c];
                ad[r] = pack2(a, a);
            }
            #pragma unroll
            for (int k = 0; k < K_; ++k) {
                float4 w4 = *reinterpret_cast<const float4*>(&sm.c.ws[(c * 4 + k) * 16 + co0]);
                double wd0 = pack2(w4.x, w4.y);
                double wd1 = pack2(w4.z, w4.w);
                #pragma unroll
                for (int i = 0; i < 4; ++i) {
                    fma2(acc2[i][0], ad[i + 2 * k], wd0);
                    fma2(acc2[i][1], ad[i + 2 * k], wd1);
                }
            }
        }

        float* ob = out + ((size_t)(b * T_) * F_ + f) * OUTC;

        // temp_out slice [16:32): bias + relu
        float4 bb = *reinterpret_cast<const float4*>(&sm.c.bs[co0]);
        #pragma unroll
        for (int i = 0; i < 4; ++i) {
            float2 q0 = unpack2(acc2[i][0]);
            float2 q1 = unpack2(acc2[i][1]);
            float4 v;
            v.x = fmaxf(q0.x + bb.x, 0.f);
            v.y = fmaxf(q0.y + bb.y, 0.f);
            v.z = fmaxf(q1.x + bb.z, 0.f);
            v.w = fmaxf(q1.y + bb.w, 0.f);
            *reinterpret_cast<float4*>(&ob[(size_t)(t0 + i) * (F_ * OUTC) + 16 + co0]) = v;
        }

        // x passthrough slice [0:16): relu(x)
        #pragma unroll
        for (int l = 0; l < 16; ++l) {
            int idx = tid + l * 256;
            int t   = idx >> 4;
            int c   = idx & 15;
            ob[(size_t)t * (F_ * OUTC) + c] = fmaxf(sm.c.xs[(t + LPAD) * 17 + c], 0.f);
        }
    }
}

// ============================================================================
// Broadcast kernel: out[row, f, 32:96] = g_point[row, :] for all 64 f.
// 2048 blocks x 256 threads, 4 rows per block. Pure streaming stores.
// ============================================================================
__global__ __launch_bounds__(256)
void tpc_bcast(float* __restrict__ out)
{
    const int tid = threadIdx.x;
    const int q   = tid & 15;              // float4 index within 64-wide P
    const int f0  = tid >> 4;              // 0..15
    const int row_base = blockIdx.x * 4;

    #pragma unroll
    for (int rr = 0; rr < 4; ++rr) {
        int row = row_base + rr;
        float4 v = *reinterpret_cast<const float4*>(&g_point[(size_t)row * P_ + q * 4]);
        float* ob = out + (size_t)row * (F_ * OUTC) + 32 + q * 4;
        #pragma unroll
        for (int ff = 0; ff < 4; ++ff) {
            int f = ff * 16 + f0;
            *reinterpret_cast<float4*>(&ob[(size_t)f * OUTC]) = v;
        }
    }
}

// ============================================================================
// Launch
// ============================================================================
extern "C" void kernel_launch(void* const* d_in, const int* in_sizes, int n_in,
                              void* d_out, int out_size)
{
    const float* x      = (const float*)d_in[0];   // [32,256,64,16]
    const float* statv  = (const float*)d_in[1];   // [32,32]
    const float* conv_w = (const float*)d_in[2];   // [64,16,16,4]
    const float* conv_b = (const float*)d_in[3];   // [64,16]
    const float* W_p    = (const float*)d_in[4];   // [1056,64]
    const float* b_p    = (const float*)d_in[5];   // [64]
    float* out = (float*)d_out;                    // [32,256,64,96]

    tpc_fused<<<PBLKS + B_ * F_, 256>>>(x, statv, conv_w, conv_b, W_p, b_p, out);
    tpc_bcast<<<ROWS / 4, 256>>>(out);
}